// round 1
// baseline (speedup 1.0000x reference)
#include <cuda_runtime.h>
#include <cstdint>

#define E_ 11
#define B_ 1024
#define D_ 1536
#define H_ 3072
#define C_ 5242

#define BM 128
#define BN 64
#define BK 32
#define NTHREADS 256
#define SA_STRIDE 36              // BK + 4 pad: conflict-free A fragment LDS
#define SB_STRIDE 72              // BN + 8 pad: conflict-free B fragment LDS
#define SA_ELEMS (BM * SA_STRIDE) // 4608 floats
#define SB_ELEMS (BK * SB_STRIDE) // 2304 floats
#define SMEM_BYTES ((2 * SA_ELEMS + 2 * SB_ELEMS) * 4) // 55296 B

// ---- scratch (device globals: no allocations allowed) ----
__device__ int   g_cnt[E_];
__device__ int   g_idx[E_ * B_];
__device__ float g_h1[(size_t)B_ * H_];
__device__ float g_h2[(size_t)B_ * H_];

// ---------------------------------------------------------------------------
// Routing: bin = trunc((1 - mask_frac) / 0.1) exactly as JAX fp32 computes it.
// Single block so the count-zeroing and the atomics are ordered by one sync.
// ---------------------------------------------------------------------------
__global__ void route_kernel(const float* __restrict__ mf) {
    int tid = threadIdx.x;
    if (tid < E_) g_cnt[tid] = 0;
    __syncthreads();
    float t = 1.0f - mf[tid];
    float q = t / 0.1f;               // IEEE div, matches XLA lowering
    int bin = (int)q;                 // trunc toward zero == astype(int32)
    bin = max(0, min(E_ - 1, bin));
    int pos = atomicAdd(&g_cnt[bin], 1);
    g_idx[bin * B_ + pos] = tid;
}

// ---- PTX helpers ----------------------------------------------------------
__device__ __forceinline__ void cp_async16(uint32_t s, const float* g) {
    asm volatile("cp.async.cg.shared.global [%0], [%1], 16;\n" :: "r"(s), "l"(g));
}
__device__ __forceinline__ void cp_async8(uint32_t s, const float* g, int bytes) {
    asm volatile("cp.async.ca.shared.global [%0], [%1], 8, %2;\n"
                 :: "r"(s), "l"(g), "r"(bytes));
}
__device__ __forceinline__ void cp_commit() {
    asm volatile("cp.async.commit_group;\n" ::: "memory");
}
template <int N>
__device__ __forceinline__ void cp_wait() {
    asm volatile("cp.async.wait_group %0;\n" :: "n"(N) : "memory");
}
__device__ __forceinline__ void mma_tf32(float c[4], const uint32_t a[4],
                                         const uint32_t b[2]) {
    asm volatile(
        "mma.sync.aligned.m16n8k8.row.col.f32.tf32.tf32.f32 "
        "{%0,%1,%2,%3}, {%4,%5,%6,%7}, {%8,%9}, {%0,%1,%2,%3};\n"
        : "+f"(c[0]), "+f"(c[1]), "+f"(c[2]), "+f"(c[3])
        : "r"(a[0]), "r"(a[1]), "r"(a[2]), "r"(a[3]), "r"(b[0]), "r"(b[1]));
}
__device__ __forceinline__ float gelu_exact(float x) {
    return 0.5f * x * (1.0f + erff(x * 0.70710678118654752f));
}

// ---------------------------------------------------------------------------
// Per-bin gather GEMM:  Cout[idx[m], :] = (gelu?)( A[idx[m], :K] @ W_e[K,N] + b_e )
// grid = (ceil(N/BN), 8, E). Blocks with m_tile*BM >= count exit immediately,
// so each expert's weights stream from HBM ~once (count<=128 typical).
// ---------------------------------------------------------------------------
template <bool DO_GELU>
__global__ void __launch_bounds__(NTHREADS, 2)
expert_gemm(const float* __restrict__ A, int lda,
            const float* __restrict__ W, const float* __restrict__ bias,
            float* __restrict__ Cout, int ldc, int K, int N)
{
    const int e = blockIdx.z;
    const int cnt = g_cnt[e];
    const int mtile = blockIdx.y;
    if (mtile * BM >= cnt) return;
    const int n0 = blockIdx.x * BN;

    const int* idxE = g_idx + e * B_;
    const float* We = W + (size_t)e * K * N;
    const float* be = bias + (size_t)e * N;

    extern __shared__ float smem[];
    float* sA = smem;                    // [2][BM][SA_STRIDE]
    float* sB = smem + 2 * SA_ELEMS;     // [2][BK][SB_STRIDE]
    const uint32_t sA_base = (uint32_t)__cvta_generic_to_shared(sA);
    const uint32_t sB_base = (uint32_t)__cvta_generic_to_shared(sB);

    const int tid = threadIdx.x;

    // ---- A (gathered rows) load setup: 4x 16B per thread per BK tile ----
    const int a_kc = (tid & 7) * 4;
    const float* a_src[4];
    uint32_t a_dst[4];
#pragma unroll
    for (int i = 0; i < 4; i++) {
        int r = (tid >> 3) + 32 * i;
        int gm = mtile * BM + r;
        int gmc = gm < cnt ? gm : cnt - 1;      // pad rows: gather a valid row
        int srow = idxE[gmc];
        a_src[i] = A + (size_t)srow * lda + a_kc;
        a_dst[i] = sA_base + (uint32_t)((r * SA_STRIDE + a_kc) * 4);
    }
    // ---- W load setup: 4x 8B per thread per BK tile (8B-aligned for N=5242) ----
    const int b_nc = (tid & 31) * 2;
    const int b_bytes = (n0 + b_nc) < N ? 8 : 0;   // zfill beyond last column
    int b_ncol = n0 + b_nc; if (b_ncol > N - 2) b_ncol = N - 2;
    const float* b_src[4];
    uint32_t b_dst[4];
#pragma unroll
    for (int i = 0; i < 4; i++) {
        int r = (tid >> 5) + 8 * i;
        b_src[i] = We + (size_t)r * N + b_ncol;
        b_dst[i] = sB_base + (uint32_t)((r * SB_STRIDE + b_nc) * 4);
    }

    const int KT = K / BK;
    auto issue = [&](int t) {
        int stage = t & 1;
        uint32_t aoff = (uint32_t)stage * (SA_ELEMS * 4);
        uint32_t boff = (uint32_t)stage * (SB_ELEMS * 4);
        size_t k0 = (size_t)t * BK;
#pragma unroll
        for (int i = 0; i < 4; i++) cp_async16(a_dst[i] + aoff, a_src[i] + k0);
#pragma unroll
        for (int i = 0; i < 4; i++) cp_async8(b_dst[i] + boff, b_src[i] + k0 * N, b_bytes);
        cp_commit();
    };
    issue(0);

    const int lane = tid & 31;
    const int warp = tid >> 5;
    const int wm = (warp & 3) * 32;   // 4 warps along M
    const int wn = (warp >> 2) * 32;  // 2 warps along N
    const int g  = lane >> 2;
    const int tg = lane & 3;

    float acc[2][4][4];
#pragma unroll
    for (int mi = 0; mi < 2; mi++)
#pragma unroll
        for (int ni = 0; ni < 4; ni++)
#pragma unroll
            for (int k = 0; k < 4; k++) acc[mi][ni][k] = 0.f;

    for (int t = 0; t < KT; t++) {
        if (t + 1 < KT) { issue(t + 1); cp_wait<1>(); }
        else           { cp_wait<0>(); }
        __syncthreads();
        const float* cA = sA + (t & 1) * SA_ELEMS;
        const float* cB = sB + (t & 1) * SB_ELEMS;
#pragma unroll
        for (int ks = 0; ks < 4; ks++) {
            uint32_t af[2][4], bf[4][2];
#pragma unroll
            for (int mi = 0; mi < 2; mi++) {
                int row = wm + mi * 16 + g;
                int col = ks * 8 + tg;
                af[mi][0] = __float_as_uint(cA[row * SA_STRIDE + col]);
                af[mi][1] = __float_as_uint(cA[(row + 8) * SA_STRIDE + col]);
                af[mi][2] = __float_as_uint(cA[row * SA_STRIDE + col + 4]);
                af[mi][3] = __float_as_uint(cA[(row + 8) * SA_STRIDE + col + 4]);
            }
#pragma unroll
            for (int ni = 0; ni < 4; ni++) {
                int coln = wn + ni * 8 + g;
                int rowk = ks * 8 + tg;
                bf[ni][0] = __float_as_uint(cB[rowk * SB_STRIDE + coln]);
                bf[ni][1] = __float_as_uint(cB[(rowk + 4) * SB_STRIDE + coln]);
            }
#pragma unroll
            for (int mi = 0; mi < 2; mi++)
#pragma unroll
                for (int ni = 0; ni < 4; ni++)
                    mma_tf32(acc[mi][ni], af[mi], bf[ni]);
        }
        __syncthreads();
    }

    // ---- epilogue: bias (+gelu) and scatter to original sample rows ----
#pragma unroll
    for (int mi = 0; mi < 2; mi++) {
#pragma unroll
        for (int half = 0; half < 2; half++) {
            int m = wm + mi * 16 + g + half * 8;
            int gm = mtile * BM + m;
            if (gm >= cnt) continue;
            int brow = idxE[gm];
            float* orow = Cout + (size_t)brow * ldc;
#pragma unroll
            for (int ni = 0; ni < 4; ni++) {
                int gn = n0 + wn + ni * 8 + tg * 2;
                float v0 = acc[mi][ni][half * 2 + 0];
                float v1 = acc[mi][ni][half * 2 + 1];
                if (gn < N) {
                    float r0 = v0 + be[gn];
                    if (DO_GELU) r0 = gelu_exact(r0);
                    orow[gn] = r0;
                }
                if (gn + 1 < N) {
                    float r1 = v1 + be[gn + 1];
                    if (DO_GELU) r1 = gelu_exact(r1);
                    orow[gn + 1] = r1;
                }
            }
        }
    }
}

// ---------------------------------------------------------------------------
// In-place row-wise log_softmax over C=5242 columns.
// ---------------------------------------------------------------------------
__global__ void logsoftmax_kernel(float* __restrict__ out) {
    const int b = blockIdx.x;
    float* row = out + (size_t)b * C_;
    __shared__ float sred[256];
    const int tid = threadIdx.x;

    float lmax = -3.4e38f;
    for (int i = tid; i < C_; i += 256) lmax = fmaxf(lmax, row[i]);
    sred[tid] = lmax;
    __syncthreads();
    for (int s = 128; s > 0; s >>= 1) {
        if (tid < s) sred[tid] = fmaxf(sred[tid], sred[tid + s]);
        __syncthreads();
    }
    const float mx = sred[0];
    __syncthreads();

    float lsum = 0.f;
    for (int i = tid; i < C_; i += 256) lsum += expf(row[i] - mx);
    sred[tid] = lsum;
    __syncthreads();
    for (int s = 128; s > 0; s >>= 1) {
        if (tid < s) sred[tid] += sred[tid + s];
        __syncthreads();
    }
    const float lse = mx + logf(sred[0]);

    for (int i = tid; i < C_; i += 256) row[i] = row[i] - lse;
}

// ---------------------------------------------------------------------------
extern "C" void kernel_launch(void* const* d_in, const int* in_sizes, int n_in,
                              void* d_out, int out_size)
{
    const float* x  = (const float*)d_in[0];
    const float* mf = (const float*)d_in[1];
    const float* W1 = (const float*)d_in[2];
    const float* b1 = (const float*)d_in[3];
    const float* W2 = (const float*)d_in[4];
    const float* b2 = (const float*)d_in[5];
    const float* W3 = (const float*)d_in[6];
    const float* b3 = (const float*)d_in[7];
    float* out = (float*)d_out;

    void *h1p = nullptr, *h2p = nullptr;
    cudaGetSymbolAddress(&h1p, g_h1);
    cudaGetSymbolAddress(&h2p, g_h2);

    cudaFuncSetAttribute(expert_gemm<true>,
                         cudaFuncAttributeMaxDynamicSharedMemorySize, SMEM_BYTES);
    cudaFuncSetAttribute(expert_gemm<false>,
                         cudaFuncAttributeMaxDynamicSharedMemorySize, SMEM_BYTES);

    route_kernel<<<1, B_>>>(mf);

    // L1: [cnt,1536] @ [1536,3072] -> gelu -> h1
    expert_gemm<true><<<dim3(H_ / BN, B_ / BM, E_), NTHREADS, SMEM_BYTES>>>(
        x, D_, W1, b1, (float*)h1p, H_, D_, H_);
    // L2: [cnt,3072] @ [3072,3072] -> gelu -> h2
    expert_gemm<true><<<dim3(H_ / BN, B_ / BM, E_), NTHREADS, SMEM_BYTES>>>(
        (float*)h1p, H_, W2, b2, (float*)h2p, H_, H_, H_);
    // L3: [cnt,3072] @ [3072,5242] + b3 -> preds (into d_out)
    expert_gemm<false><<<dim3((C_ + BN - 1) / BN, B_ / BM, E_), NTHREADS, SMEM_BYTES>>>(
        (float*)h2p, H_, W3, b3, out, C_, H_, C_);
    // log_softmax in place
    logsoftmax_kernel<<<B_, 256>>>(out);
}